// round 5
// baseline (speedup 1.0000x reference)
#include <cuda_runtime.h>
#include <math.h>

#define THREADS 128
#define NJ 12

// Output layout (flattened tuple, float32):
//   outs : [B][3][4][4]  at offset 0            (B*48)
//   revls: [B][12][6]    at offset B*48         (B*72)
//   prils: [B][12][6]    at offset B*120        (B*72)

__global__ __launch_bounds__(THREADS, 6) void poe_kernel(
    const float* __restrict__ q,
    const float* __restrict__ rev,
    const float* __restrict__ pri,
    const float* __restrict__ pos,
    const float* __restrict__ ori,
    float* __restrict__ out, int B)
{
    __shared__ float s_tw[24 * 24];   // per-twist constants
    __shared__ float s_tool[3 * 12];

    const int tid = threadIdx.x;
    const int b0 = blockIdx.x * THREADS;

    // ---------------- setup: twist constants ----------------
    if (tid < 24) {
        int j = tid >> 1;
        const float* xi = (tid & 1) ? (pri + j * 6) : (rev + j * 6);
        float wx = xi[0], wy = xi[1], wz = xi[2];
        float vx = xi[3], vy = xi[4], vz = xi[5];
        float ww = wx * wx + wy * wy + wz * wz;
        float a2 = ww + 1e-12f;
        float a = sqrtf(a2);
        float inva = 1.0f / a;
        float inva2 = 1.0f / a2;
        float* t = s_tw + tid * 24;
        t[0] = wx; t[1] = wy; t[2] = wz;
        t[3] = vx; t[4] = vy; t[5] = vz;
        t[6] = a;
        // hat(w)^2 = w w^T - (w.w) I  (exact ww — matches wh@wh)
        float W2xx = wx * wx - ww, W2xy = wx * wy, W2xz = wx * wz;
        float W2yy = wy * wy - ww, W2yz = wy * wz, W2zz = wz * wz - ww;
        t[7] = W2xx; t[8] = W2xy; t[9] = W2xz;
        t[10] = W2yy; t[11] = W2yz; t[12] = W2zz;
        // w x v
        t[13] = wy * vz - wz * vy;
        t[14] = wz * vx - wx * vz;
        t[15] = wx * vy - wy * vx;
        // hat(w)^2 @ v
        t[16] = W2xx * vx + W2xy * vy + W2xz * vz;
        t[17] = W2xy * vx + W2yy * vy + W2yz * vz;
        t[18] = W2xz * vx + W2yz * vy + W2zz * vz;
        t[19] = inva;
        t[20] = inva2;
        t[21] = inva * inva2;
    } else if (tid < 27) {
        // tool matrices for branch joints 3, 7, 11 (precise sincos — one-time)
        int k = tid - 24;
        int idx = 4 * k + 3;
        float rr = ori[idx * 3 + 0], pp = ori[idx * 3 + 1], yy = ori[idx * 3 + 2];
        float cr, sr, cp, sp, cy, sy;
        sincosf(rr, &sr, &cr);
        sincosf(pp, &sp, &cp);
        sincosf(yy, &sy, &cy);
        float* tl = s_tool + k * 12;
        tl[0] = cy * cp; tl[1] = cy * sp * sr - sy * cr; tl[2] = cy * sp * cr + sy * sr;
        tl[3] = sy * cp; tl[4] = sy * sp * sr + cy * cr; tl[5] = sy * sp * cr - cy * sr;
        tl[6] = -sp;     tl[7] = cp * sr;                tl[8] = cp * cr;
        tl[9] = pos[idx * 3 + 0]; tl[10] = pos[idx * 3 + 1]; tl[11] = pos[idx * 3 + 2];
    }
    __syncthreads();

    const long long b = (long long)b0 + tid;
    if (b >= B) return;

    const float* qb = q + b * 24;
    float* revg = out + (long long)B * 48 + b * 72;
    float* prig = out + (long long)B * 120 + b * 72;

    // persistent transform state
    float R00 = 1.f, R01 = 0.f, R02 = 0.f;
    float R10 = 0.f, R11 = 1.f, R12 = 0.f;
    float R20 = 0.f, R21 = 0.f, R22 = 1.f;
    float px = 0.f, py = 0.f, pz = 0.f;

    #pragma unroll
    for (int j = 0; j < NJ; j++) {
        #pragma unroll
        for (int half = 0; half < 2; half++) {
            const float* t = s_tw + (2 * j + half) * 24;
            float wx = t[0], wy = t[1], wz = t[2];
            float vx = t[3], vy = t[4], vz = t[5];

            // ---- adj_inv(T) applied to xi -> (wp, vp) ----
            float wpx = R00 * wx + R10 * wy + R20 * wz;
            float wpy = R01 * wx + R11 * wy + R21 * wz;
            float wpz = R02 * wx + R12 * wy + R22 * wz;
            float ux = vx - (py * wz - pz * wy);
            float uy = vy - (pz * wx - px * wz);
            float uz = vz - (px * wy - py * wx);
            float vpx = R00 * ux + R10 * uy + R20 * uz;
            float vpy = R01 * ux + R11 * uy + R21 * uz;
            float vpz = R02 * ux + R12 * uy + R22 * uz;

            // direct global store: 3x STG.64, lines aggregate in L2
            float2* sdst = (float2*)((half ? prig : revg) + j * 6);
            sdst[0] = make_float2(wpx, wpy);
            sdst[1] = make_float2(wpz, vpx);
            sdst[2] = make_float2(vpy, vpz);

            // ---- E = exp(xi * th) ----
            float th = __ldg(qb + 2 * j + half);
            float ang = t[6] * th;
            float s, c;
            __sincosf(ang, &s, &c);
            float k1 = s * t[19];
            float k2 = (1.0f - c) * t[20];
            float k3 = (ang - s) * t[21];
            float E00 = 1.f + k2 * t[7];
            float E01 = -k1 * wz + k2 * t[8];
            float E02 =  k1 * wy + k2 * t[9];
            float E10 =  k1 * wz + k2 * t[8];
            float E11 = 1.f + k2 * t[10];
            float E12 = -k1 * wx + k2 * t[11];
            float E20 = -k1 * wy + k2 * t[9];
            float E21 =  k1 * wx + k2 * t[11];
            float E22 = 1.f + k2 * t[12];
            float ex = th * vx + k2 * t[13] + k3 * t[16];
            float ey = th * vy + k2 * t[14] + k3 * t[17];
            float ez = th * vz + k2 * t[15] + k3 * t[18];

            // ---- T = T * E ----
            float npx = px + R00 * ex + R01 * ey + R02 * ez;
            float npy = py + R10 * ex + R11 * ey + R12 * ez;
            float npz = pz + R20 * ex + R21 * ey + R22 * ez;
            float n00 = R00 * E00 + R01 * E10 + R02 * E20;
            float n01 = R00 * E01 + R01 * E11 + R02 * E21;
            float n02 = R00 * E02 + R01 * E12 + R02 * E22;
            float n10 = R10 * E00 + R11 * E10 + R12 * E20;
            float n11 = R10 * E01 + R11 * E11 + R12 * E21;
            float n12 = R10 * E02 + R11 * E12 + R12 * E22;
            float n20 = R20 * E00 + R21 * E10 + R22 * E20;
            float n21 = R20 * E01 + R21 * E11 + R22 * E21;
            float n22 = R20 * E02 + R21 * E12 + R22 * E22;
            R00 = n00; R01 = n01; R02 = n02;
            R10 = n10; R11 = n11; R12 = n12;
            R20 = n20; R21 = n21; R22 = n22;
            px = npx; py = npy; pz = npz;
        }

        // branch outputs at j = 3, 7, 11
        if ((j & 3) == 3) {
            int k = j >> 2;
            const float* tl = s_tool + k * 12;
            float O00 = R00 * tl[0] + R01 * tl[3] + R02 * tl[6];
            float O01 = R00 * tl[1] + R01 * tl[4] + R02 * tl[7];
            float O02 = R00 * tl[2] + R01 * tl[5] + R02 * tl[8];
            float O10 = R10 * tl[0] + R11 * tl[3] + R12 * tl[6];
            float O11 = R10 * tl[1] + R11 * tl[4] + R12 * tl[7];
            float O12 = R10 * tl[2] + R11 * tl[5] + R12 * tl[8];
            float O20 = R20 * tl[0] + R21 * tl[3] + R22 * tl[6];
            float O21 = R20 * tl[1] + R21 * tl[4] + R22 * tl[7];
            float O22 = R20 * tl[2] + R21 * tl[5] + R22 * tl[8];
            float pox = R00 * tl[9] + R01 * tl[10] + R02 * tl[11] + px;
            float poy = R10 * tl[9] + R11 * tl[10] + R12 * tl[11] + py;
            float poz = R20 * tl[9] + R21 * tl[10] + R22 * tl[11] + pz;
            float4* dst = (float4*)(out + b * 48 + k * 16);
            dst[0] = make_float4(O00, O01, O02, pox);
            dst[1] = make_float4(O10, O11, O12, poy);
            dst[2] = make_float4(O20, O21, O22, poz);
            dst[3] = make_float4(0.f, 0.f, 0.f, 1.f);
        }
    }
}

extern "C" void kernel_launch(void* const* d_in, const int* in_sizes, int n_in,
                              void* d_out, int out_size)
{
    const float* q   = (const float*)d_in[0];
    const float* rev = (const float*)d_in[1];
    const float* pri = (const float*)d_in[2];
    const float* pos = (const float*)d_in[3];
    const float* ori = (const float*)d_in[4];
    float* out = (float*)d_out;
    int B = in_sizes[0] / 24;
    int grid = (B + THREADS - 1) / THREADS;
    poe_kernel<<<grid, THREADS>>>(q, rev, pri, pos, ori, out, B);
}

// round 6
// speedup vs baseline: 2.9665x; 2.9665x over previous
#include <cuda_runtime.h>
#include <math.h>

#define THREADS 64
#define STRIDE 37   // 36 chunk floats + 1 pad (bank-conflict-free: gcd(37,32)=1)

// Output layout (flattened tuple, float32):
//   outs : [B][3][4][4]  at offset 0            (B*48)
//   revls: [B][12][6]    at offset B*48         (B*72)
//   prils: [B][12][6]    at offset B*120        (B*72)

__global__ __launch_bounds__(THREADS, 10) void poe_kernel(
    const float* __restrict__ q,
    const float* __restrict__ rev,
    const float* __restrict__ pri,
    const float* __restrict__ pos,
    const float* __restrict__ ori,
    float* __restrict__ out, int B)
{
    __shared__ float s_tw[24 * 24];
    __shared__ float s_tool[3 * 12];
    __shared__ float s_rev[THREADS * STRIDE];
    __shared__ float s_pri[THREADS * STRIDE];

    const int tid = threadIdx.x;
    const int b0 = blockIdx.x * THREADS;

    // ---------------- setup: twist constants ----------------
    if (tid < 24) {
        int j = tid >> 1;
        const float* xi = (tid & 1) ? (pri + j * 6) : (rev + j * 6);
        float wx = xi[0], wy = xi[1], wz = xi[2];
        float vx = xi[3], vy = xi[4], vz = xi[5];
        float ww = wx * wx + wy * wy + wz * wz;
        float a2 = ww + 1e-12f;
        float a = sqrtf(a2);
        float inva = 1.0f / a;
        float inva2 = 1.0f / a2;
        float* t = s_tw + tid * 24;
        t[0] = wx; t[1] = wy; t[2] = wz;
        t[3] = vx; t[4] = vy; t[5] = vz;
        t[6] = a;
        // hat(w)^2 = w w^T - (w.w) I  (exact ww — matches wh@wh)
        float W2xx = wx * wx - ww, W2xy = wx * wy, W2xz = wx * wz;
        float W2yy = wy * wy - ww, W2yz = wy * wz, W2zz = wz * wz - ww;
        t[7] = W2xx; t[8] = W2xy; t[9] = W2xz;
        t[10] = W2yy; t[11] = W2yz; t[12] = W2zz;
        // w x v
        t[13] = wy * vz - wz * vy;
        t[14] = wz * vx - wx * vz;
        t[15] = wx * vy - wy * vx;
        // hat(w)^2 @ v
        t[16] = W2xx * vx + W2xy * vy + W2xz * vz;
        t[17] = W2xy * vx + W2yy * vy + W2yz * vz;
        t[18] = W2xz * vx + W2yz * vy + W2zz * vz;
        t[19] = inva;
        t[20] = inva2;
        t[21] = inva * inva2;
    } else if (tid < 27) {
        // tool matrices for branch joints 3, 7, 11 (precise sincos — one-time)
        int k = tid - 24;
        int idx = 4 * k + 3;
        float rr = ori[idx * 3 + 0], pp = ori[idx * 3 + 1], yy = ori[idx * 3 + 2];
        float cr, sr, cp, sp, cy, sy;
        sincosf(rr, &sr, &cr);
        sincosf(pp, &sp, &cp);
        sincosf(yy, &sy, &cy);
        float* tl = s_tool + k * 12;
        tl[0] = cy * cp; tl[1] = cy * sp * sr - sy * cr; tl[2] = cy * sp * cr + sy * sr;
        tl[3] = sy * cp; tl[4] = sy * sp * sr + cy * cr; tl[5] = sy * sp * cr - cy * sr;
        tl[6] = -sp;     tl[7] = cp * sr;                tl[8] = cp * cr;
        tl[9] = pos[idx * 3 + 0]; tl[10] = pos[idx * 3 + 1]; tl[11] = pos[idx * 3 + 2];
    }
    __syncthreads();

    const long long b = (long long)b0 + tid;
    const bool active = (b < B);
    const int nel = min(B - b0, THREADS);
    const float* qb = q + b * 24;
    float* revg = out + (long long)B * 48 + (long long)b0 * 72;
    float* prig = out + (long long)B * 120 + (long long)b0 * 72;

    // persistent transform state
    float R00 = 1.f, R01 = 0.f, R02 = 0.f;
    float R10 = 0.f, R11 = 1.f, R12 = 0.f;
    float R20 = 0.f, R21 = 0.f, R22 = 1.f;
    float px = 0.f, py = 0.f, pz = 0.f;

    float* srevBase = s_rev + tid * STRIDE;
    float* spriBase = s_pri + tid * STRIDE;

    #pragma unroll
    for (int jc = 0; jc < 2; jc++) {     // 6 joints per chunk
        if (active) {
            #pragma unroll
            for (int jj = 0; jj < 6; jj++) {
                int j = jc * 6 + jj;
                #pragma unroll
                for (int half = 0; half < 2; half++) {
                    const float* t = s_tw + (2 * j + half) * 24;
                    float wx = t[0], wy = t[1], wz = t[2];
                    float vx = t[3], vy = t[4], vz = t[5];

                    // adj_inv(T) applied to xi
                    float wpx = R00 * wx + R10 * wy + R20 * wz;
                    float wpy = R01 * wx + R11 * wy + R21 * wz;
                    float wpz = R02 * wx + R12 * wy + R22 * wz;
                    float ux = vx - (py * wz - pz * wy);
                    float uy = vy - (pz * wx - px * wz);
                    float uz = vz - (px * wy - py * wx);
                    float vpx = R00 * ux + R10 * uy + R20 * uz;
                    float vpy = R01 * ux + R11 * uy + R21 * uz;
                    float vpz = R02 * ux + R12 * uy + R22 * uz;
                    float* sdst = (half ? spriBase : srevBase) + jj * 6;
                    sdst[0] = wpx; sdst[1] = wpy; sdst[2] = wpz;
                    sdst[3] = vpx; sdst[4] = vpy; sdst[5] = vpz;

                    // E = exp(xi * th)
                    float th = __ldg(qb + 2 * j + half);
                    float ang = t[6] * th;
                    float s, c;
                    __sincosf(ang, &s, &c);
                    float k1 = s * t[19];
                    float k2 = (1.0f - c) * t[20];
                    float k3 = (ang - s) * t[21];
                    float E00 = 1.f + k2 * t[7];
                    float E01 = -k1 * wz + k2 * t[8];
                    float E02 =  k1 * wy + k2 * t[9];
                    float E10 =  k1 * wz + k2 * t[8];
                    float E11 = 1.f + k2 * t[10];
                    float E12 = -k1 * wx + k2 * t[11];
                    float E20 = -k1 * wy + k2 * t[9];
                    float E21 =  k1 * wx + k2 * t[11];
                    float E22 = 1.f + k2 * t[12];
                    float ex = th * vx + k2 * t[13] + k3 * t[16];
                    float ey = th * vy + k2 * t[14] + k3 * t[17];
                    float ez = th * vz + k2 * t[15] + k3 * t[18];

                    // T = T * E
                    float npx = px + R00 * ex + R01 * ey + R02 * ez;
                    float npy = py + R10 * ex + R11 * ey + R12 * ez;
                    float npz = pz + R20 * ex + R21 * ey + R22 * ez;
                    float n00 = R00 * E00 + R01 * E10 + R02 * E20;
                    float n01 = R00 * E01 + R01 * E11 + R02 * E21;
                    float n02 = R00 * E02 + R01 * E12 + R02 * E22;
                    float n10 = R10 * E00 + R11 * E10 + R12 * E20;
                    float n11 = R10 * E01 + R11 * E11 + R12 * E21;
                    float n12 = R10 * E02 + R11 * E12 + R12 * E22;
                    float n20 = R20 * E00 + R21 * E10 + R22 * E20;
                    float n21 = R20 * E01 + R21 * E11 + R22 * E21;
                    float n22 = R20 * E02 + R21 * E12 + R22 * E22;
                    R00 = n00; R01 = n01; R02 = n02;
                    R10 = n10; R11 = n11; R12 = n12;
                    R20 = n20; R21 = n21; R22 = n22;
                    px = npx; py = npy; pz = npz;

                    // branch outputs at j = 3, 7, 11 (after both halves)
                    if (half == 1 && (j & 3) == 3) {
                        int k = j >> 2;
                        const float* tl = s_tool + k * 12;
                        float O00 = R00 * tl[0] + R01 * tl[3] + R02 * tl[6];
                        float O01 = R00 * tl[1] + R01 * tl[4] + R02 * tl[7];
                        float O02 = R00 * tl[2] + R01 * tl[5] + R02 * tl[8];
                        float O10 = R10 * tl[0] + R11 * tl[3] + R12 * tl[6];
                        float O11 = R10 * tl[1] + R11 * tl[4] + R12 * tl[7];
                        float O12 = R10 * tl[2] + R11 * tl[5] + R12 * tl[8];
                        float O20 = R20 * tl[0] + R21 * tl[3] + R22 * tl[6];
                        float O21 = R20 * tl[1] + R21 * tl[4] + R22 * tl[7];
                        float O22 = R20 * tl[2] + R21 * tl[5] + R22 * tl[8];
                        float pox = R00 * tl[9] + R01 * tl[10] + R02 * tl[11] + px;
                        float poy = R10 * tl[9] + R11 * tl[10] + R12 * tl[11] + py;
                        float poz = R20 * tl[9] + R21 * tl[10] + R22 * tl[11] + pz;
                        float4* dst = (float4*)(out + b * 48 + k * 16);
                        dst[0] = make_float4(O00, O01, O02, pox);
                        dst[1] = make_float4(O10, O11, O12, poy);
                        dst[2] = make_float4(O20, O21, O22, poz);
                        dst[3] = make_float4(0.f, 0.f, 0.f, 1.f);
                    }
                }
            }
        }
        __syncthreads();

        // ---- flush this 6-joint chunk (fully coalesced float4 stores) ----
        if (nel == THREADS) {
            float4* r4 = (float4*)revg;
            float4* p4 = (float4*)prig;
            #pragma unroll
            for (int i4 = tid; i4 < THREADS * 9; i4 += THREADS) {
                int e = i4 / 9, r = i4 - e * 9;       // 9 float4 = 36 floats per element
                int gidx = e * 18 + jc * 9 + r;       // element block = 18 float4
                const float* sa = s_rev + e * STRIDE + r * 4;
                r4[gidx] = make_float4(sa[0], sa[1], sa[2], sa[3]);
                const float* sb = s_pri + e * STRIDE + r * 4;
                p4[gidx] = make_float4(sb[0], sb[1], sb[2], sb[3]);
            }
        } else {
            for (int i = tid; i < nel * 36; i += THREADS) {
                int e = i / 36, r = i - e * 36;
                revg[e * 72 + jc * 36 + r] = s_rev[e * STRIDE + r];
                prig[e * 72 + jc * 36 + r] = s_pri[e * STRIDE + r];
            }
        }
        if (jc == 0) __syncthreads();   // buffer reuse by chunk 1
    }
}

extern "C" void kernel_launch(void* const* d_in, const int* in_sizes, int n_in,
                              void* d_out, int out_size)
{
    const float* q   = (const float*)d_in[0];
    const float* rev = (const float*)d_in[1];
    const float* pri = (const float*)d_in[2];
    const float* pos = (const float*)d_in[3];
    const float* ori = (const float*)d_in[4];
    float* out = (float*)d_out;
    int B = in_sizes[0] / 24;
    int grid = (B + THREADS - 1) / THREADS;
    poe_kernel<<<grid, THREADS>>>(q, rev, pri, pos, ori, out, B);
}

// round 7
// speedup vs baseline: 3.1130x; 1.0494x over previous
#include <cuda_runtime.h>
#include <math.h>

#define THREADS 64
#define QSTRIDE 25   // 24 q values + 1 pad (conflict-free)
#define CSTRIDE 37   // 36 chunk floats + 1 pad (conflict-free)

// Output layout (flattened tuple, float32):
//   outs : [B][3][4][4]  at offset 0            (B*48)
//   revls: [B][12][6]    at offset B*48         (B*72)
//   prils: [B][12][6]    at offset B*120        (B*72)

// constants: [24 twists][24 floats] + [3 tools][12 floats] = 612 floats
__device__ float g_scratch[612];
__constant__ float c_all[612];

__global__ void prep_kernel(
    const float* __restrict__ rev,
    const float* __restrict__ pri,
    const float* __restrict__ pos,
    const float* __restrict__ ori)
{
    int tid = threadIdx.x;
    if (tid < 24) {
        int j = tid >> 1;
        const float* xi = (tid & 1) ? (pri + j * 6) : (rev + j * 6);
        float wx = xi[0], wy = xi[1], wz = xi[2];
        float vx = xi[3], vy = xi[4], vz = xi[5];
        float ww = wx * wx + wy * wy + wz * wz;
        float a2 = ww + 1e-12f;
        float a = sqrtf(a2);
        float inva = 1.0f / a;
        float inva2 = 1.0f / a2;
        float* t = g_scratch + tid * 24;
        t[0] = wx; t[1] = wy; t[2] = wz;
        t[3] = vx; t[4] = vy; t[5] = vz;
        t[6] = a;
        // hat(w)^2 = w w^T - (w.w) I  (exact ww — matches wh@wh)
        float W2xx = wx * wx - ww, W2xy = wx * wy, W2xz = wx * wz;
        float W2yy = wy * wy - ww, W2yz = wy * wz, W2zz = wz * wz - ww;
        t[7] = W2xx; t[8] = W2xy; t[9] = W2xz;
        t[10] = W2yy; t[11] = W2yz; t[12] = W2zz;
        t[13] = wy * vz - wz * vy;
        t[14] = wz * vx - wx * vz;
        t[15] = wx * vy - wy * vx;
        t[16] = W2xx * vx + W2xy * vy + W2xz * vz;
        t[17] = W2xy * vx + W2yy * vy + W2yz * vz;
        t[18] = W2xz * vx + W2yz * vy + W2zz * vz;
        t[19] = inva;
        t[20] = inva2;
        t[21] = inva * inva2;
        t[22] = 0.f; t[23] = 0.f;
    } else if (tid < 27) {
        int k = tid - 24;
        int idx = 4 * k + 3;
        float rr = ori[idx * 3 + 0], pp = ori[idx * 3 + 1], yy = ori[idx * 3 + 2];
        float cr, sr, cp, sp, cy, sy;
        sincosf(rr, &sr, &cr);
        sincosf(pp, &sp, &cp);
        sincosf(yy, &sy, &cy);
        float* tl = g_scratch + 576 + k * 12;
        tl[0] = cy * cp; tl[1] = cy * sp * sr - sy * cr; tl[2] = cy * sp * cr + sy * sr;
        tl[3] = sy * cp; tl[4] = sy * sp * sr + cy * cr; tl[5] = sy * sp * cr - cy * sr;
        tl[6] = -sp;     tl[7] = cp * sr;                tl[8] = cp * cr;
        tl[9] = pos[idx * 3 + 0]; tl[10] = pos[idx * 3 + 1]; tl[11] = pos[idx * 3 + 2];
    }
}

__global__ __launch_bounds__(THREADS, 8) void poe_kernel(
    const float* __restrict__ q,
    float* __restrict__ out, int B)
{
    __shared__ float s_q[THREADS * QSTRIDE];
    __shared__ float s_rev[THREADS * CSTRIDE];
    __shared__ float s_pri[THREADS * CSTRIDE];

    const int tid = threadIdx.x;
    const int b0 = blockIdx.x * THREADS;
    const int nel = min(B - b0, THREADS);

    // ---------------- stage q into shared (coalesced) ----------------
    if (nel == THREADS) {
        const float4* gq = (const float4*)(q + (long long)b0 * 24);
        #pragma unroll
        for (int i4 = tid; i4 < THREADS * 24 / 4; i4 += THREADS) {
            float4 v = gq[i4];
            int i = i4 * 4;
            int e = i / 24, r = i - e * 24;
            float* d = s_q + e * QSTRIDE + r;
            d[0] = v.x; d[1] = v.y; d[2] = v.z; d[3] = v.w;
        }
    } else {
        for (int i = tid; i < nel * 24; i += THREADS) {
            int e = i / 24, r = i - e * 24;
            s_q[e * QSTRIDE + r] = q[(long long)b0 * 24 + i];
        }
    }
    __syncthreads();

    const long long b = (long long)b0 + tid;
    const bool active = (b < B);
    const float* sqBase = s_q + tid * QSTRIDE;
    float* srevBase = s_rev + tid * CSTRIDE;
    float* spriBase = s_pri + tid * CSTRIDE;
    float* revg = out + (long long)B * 48 + (long long)b0 * 72;
    float* prig = out + (long long)B * 120 + (long long)b0 * 72;

    // persistent transform state
    float R00 = 1.f, R01 = 0.f, R02 = 0.f;
    float R10 = 0.f, R11 = 1.f, R12 = 0.f;
    float R20 = 0.f, R21 = 0.f, R22 = 1.f;
    float px = 0.f, py = 0.f, pz = 0.f;

    #pragma unroll
    for (int jc = 0; jc < 2; jc++) {     // 6 joints per chunk
        if (active) {
            #pragma unroll
            for (int jj = 0; jj < 6; jj++) {
                int j = jc * 6 + jj;
                #pragma unroll
                for (int half = 0; half < 2; half++) {
                    const float* t = c_all + (2 * j + half) * 24;  // LDC, imm offsets
                    float wx = t[0], wy = t[1], wz = t[2];
                    float vx = t[3], vy = t[4], vz = t[5];

                    // adj_inv(T) applied to xi
                    float wpx = R00 * wx + R10 * wy + R20 * wz;
                    float wpy = R01 * wx + R11 * wy + R21 * wz;
                    float wpz = R02 * wx + R12 * wy + R22 * wz;
                    float ux = vx - (py * wz - pz * wy);
                    float uy = vy - (pz * wx - px * wz);
                    float uz = vz - (px * wy - py * wx);
                    float vpx = R00 * ux + R10 * uy + R20 * uz;
                    float vpy = R01 * ux + R11 * uy + R21 * uz;
                    float vpz = R02 * ux + R12 * uy + R22 * uz;
                    float* sdst = (half ? spriBase : srevBase) + jj * 6;
                    sdst[0] = wpx; sdst[1] = wpy; sdst[2] = wpz;
                    sdst[3] = vpx; sdst[4] = vpy; sdst[5] = vpz;

                    // E = exp(xi * th)
                    float th = sqBase[2 * j + half];
                    float ang = t[6] * th;
                    float s, c;
                    __sincosf(ang, &s, &c);
                    float k1 = s * t[19];
                    float k2 = (1.0f - c) * t[20];
                    float k3 = (ang - s) * t[21];
                    float E00 = 1.f + k2 * t[7];
                    float E01 = -k1 * wz + k2 * t[8];
                    float E02 =  k1 * wy + k2 * t[9];
                    float E10 =  k1 * wz + k2 * t[8];
                    float E11 = 1.f + k2 * t[10];
                    float E12 = -k1 * wx + k2 * t[11];
                    float E20 = -k1 * wy + k2 * t[9];
                    float E21 =  k1 * wx + k2 * t[11];
                    float E22 = 1.f + k2 * t[12];
                    float ex = th * vx + k2 * t[13] + k3 * t[16];
                    float ey = th * vy + k2 * t[14] + k3 * t[17];
                    float ez = th * vz + k2 * t[15] + k3 * t[18];

                    // T = T * E
                    float npx = px + R00 * ex + R01 * ey + R02 * ez;
                    float npy = py + R10 * ex + R11 * ey + R12 * ez;
                    float npz = pz + R20 * ex + R21 * ey + R22 * ez;
                    float n00 = R00 * E00 + R01 * E10 + R02 * E20;
                    float n01 = R00 * E01 + R01 * E11 + R02 * E21;
                    float n02 = R00 * E02 + R01 * E12 + R02 * E22;
                    float n10 = R10 * E00 + R11 * E10 + R12 * E20;
                    float n11 = R10 * E01 + R11 * E11 + R12 * E21;
                    float n12 = R10 * E02 + R11 * E12 + R12 * E22;
                    float n20 = R20 * E00 + R21 * E10 + R22 * E20;
                    float n21 = R20 * E01 + R21 * E11 + R22 * E21;
                    float n22 = R20 * E02 + R21 * E12 + R22 * E22;
                    R00 = n00; R01 = n01; R02 = n02;
                    R10 = n10; R11 = n11; R12 = n12;
                    R20 = n20; R21 = n21; R22 = n22;
                    px = npx; py = npy; pz = npz;

                    // branch outputs at j = 3, 7, 11
                    if (half == 1 && (j & 3) == 3) {
                        int k = j >> 2;
                        const float* tl = c_all + 576 + k * 12;
                        float O00 = R00 * tl[0] + R01 * tl[3] + R02 * tl[6];
                        float O01 = R00 * tl[1] + R01 * tl[4] + R02 * tl[7];
                        float O02 = R00 * tl[2] + R01 * tl[5] + R02 * tl[8];
                        float O10 = R10 * tl[0] + R11 * tl[3] + R12 * tl[6];
                        float O11 = R10 * tl[1] + R11 * tl[4] + R12 * tl[7];
                        float O12 = R10 * tl[2] + R11 * tl[5] + R12 * tl[8];
                        float O20 = R20 * tl[0] + R21 * tl[3] + R22 * tl[6];
                        float O21 = R20 * tl[1] + R21 * tl[4] + R22 * tl[7];
                        float O22 = R20 * tl[2] + R21 * tl[5] + R22 * tl[8];
                        float pox = R00 * tl[9] + R01 * tl[10] + R02 * tl[11] + px;
                        float poy = R10 * tl[9] + R11 * tl[10] + R12 * tl[11] + py;
                        float poz = R20 * tl[9] + R21 * tl[10] + R22 * tl[11] + pz;
                        float4* dst = (float4*)(out + b * 48 + k * 16);
                        dst[0] = make_float4(O00, O01, O02, pox);
                        dst[1] = make_float4(O10, O11, O12, poy);
                        dst[2] = make_float4(O20, O21, O22, poz);
                        dst[3] = make_float4(0.f, 0.f, 0.f, 1.f);
                    }
                }
            }
        }
        __syncthreads();

        // ---- flush this 6-joint chunk (coalesced float4 global stores) ----
        if (nel == THREADS) {
            float4* r4 = (float4*)revg;
            float4* p4 = (float4*)prig;
            #pragma unroll
            for (int i4 = tid; i4 < THREADS * 9; i4 += THREADS) {
                int e = i4 / 9, r = i4 - e * 9;       // 9 float4 = 36 floats per element
                int gidx = e * 18 + jc * 9 + r;       // element block = 18 float4
                const float* sa = s_rev + e * CSTRIDE + r * 4;
                r4[gidx] = make_float4(sa[0], sa[1], sa[2], sa[3]);
                const float* sb = s_pri + e * CSTRIDE + r * 4;
                p4[gidx] = make_float4(sb[0], sb[1], sb[2], sb[3]);
            }
        } else {
            for (int i = tid; i < nel * 36; i += THREADS) {
                int e = i / 36, r = i - e * 36;
                revg[e * 72 + jc * 36 + r] = s_rev[e * CSTRIDE + r];
                prig[e * 72 + jc * 36 + r] = s_pri[e * CSTRIDE + r];
            }
        }
        if (jc == 0) __syncthreads();   // staging buffers reused by chunk 1
    }
}

extern "C" void kernel_launch(void* const* d_in, const int* in_sizes, int n_in,
                              void* d_out, int out_size)
{
    const float* q   = (const float*)d_in[0];
    const float* rev = (const float*)d_in[1];
    const float* pri = (const float*)d_in[2];
    const float* pos = (const float*)d_in[3];
    const float* ori = (const float*)d_in[4];
    float* out = (float*)d_out;
    int B = in_sizes[0] / 24;

    // 1) derive twist/tool constants on device
    prep_kernel<<<1, 32>>>(rev, pri, pos, ori);

    // 2) D2D async copy into constant bank (graph-capturable memcpy node)
    void* src = nullptr;
    cudaGetSymbolAddress(&src, g_scratch);
    cudaMemcpyToSymbolAsync(c_all, src, 612 * sizeof(float), 0,
                            cudaMemcpyDeviceToDevice, 0);

    // 3) main kernel
    int grid = (B + THREADS - 1) / THREADS;
    poe_kernel<<<grid, THREADS>>>(q, out, B);
}

// round 8
// speedup vs baseline: 4.2726x; 1.3725x over previous
#include <cuda_runtime.h>
#include <math.h>

#define THREADS 64
#define QSTRIDE 25   // 24 q values + 1 pad (conflict-free)
#define CSTRIDE 25   // 4 joints * 6 floats + 1 pad (conflict-free)

// Output layout (flattened tuple, float32):
//   outs : [B][3][4][4]  at offset 0            (B*48)
//   revls: [B][12][6]    at offset B*48         (B*72)
//   prils: [B][12][6]    at offset B*120        (B*72)

__global__ __launch_bounds__(THREADS, 10) void poe_kernel(
    const float* __restrict__ q,
    const float* __restrict__ rev,
    const float* __restrict__ pri,
    const float* __restrict__ pos,
    const float* __restrict__ ori,
    float* __restrict__ out, int B)
{
    __shared__ float s_tw[24 * 24];          // per-twist constants (2.3 KB)
    __shared__ float s_tool[3 * 12];
    __shared__ float s_q[THREADS * QSTRIDE]; // 6.4 KB
    __shared__ float s_rev[THREADS * CSTRIDE]; // 6.4 KB
    __shared__ float s_pri[THREADS * CSTRIDE]; // 6.4 KB

    const int tid = threadIdx.x;
    const int b0 = blockIdx.x * THREADS;
    const int nel = min(B - b0, THREADS);

    // ---------------- setup: twist constants ----------------
    if (tid < 24) {
        int j = tid >> 1;
        const float* xi = (tid & 1) ? (pri + j * 6) : (rev + j * 6);
        float wx = xi[0], wy = xi[1], wz = xi[2];
        float vx = xi[3], vy = xi[4], vz = xi[5];
        float ww = wx * wx + wy * wy + wz * wz;
        float a2 = ww + 1e-12f;
        float a = sqrtf(a2);
        float inva = 1.0f / a;
        float inva2 = 1.0f / a2;
        float* t = s_tw + tid * 24;
        t[0] = wx; t[1] = wy; t[2] = wz;
        t[3] = vx; t[4] = vy; t[5] = vz;
        t[6] = a;
        // hat(w)^2 = w w^T - (w.w) I  (exact ww — matches wh@wh)
        float W2xx = wx * wx - ww, W2xy = wx * wy, W2xz = wx * wz;
        float W2yy = wy * wy - ww, W2yz = wy * wz, W2zz = wz * wz - ww;
        t[7] = W2xx; t[8] = W2xy; t[9] = W2xz;
        t[10] = W2yy; t[11] = W2yz; t[12] = W2zz;
        t[13] = wy * vz - wz * vy;
        t[14] = wz * vx - wx * vz;
        t[15] = wx * vy - wy * vx;
        t[16] = W2xx * vx + W2xy * vy + W2xz * vz;
        t[17] = W2xy * vx + W2yy * vy + W2yz * vz;
        t[18] = W2xz * vx + W2yz * vy + W2zz * vz;
        t[19] = inva;
        t[20] = inva2;
        t[21] = inva * inva2;
    } else if (tid < 27) {
        int k = tid - 24;
        int idx = 4 * k + 3;
        float rr = ori[idx * 3 + 0], pp = ori[idx * 3 + 1], yy = ori[idx * 3 + 2];
        float cr, sr, cp, sp, cy, sy;
        sincosf(rr, &sr, &cr);
        sincosf(pp, &sp, &cp);
        sincosf(yy, &sy, &cy);
        float* tl = s_tool + k * 12;
        tl[0] = cy * cp; tl[1] = cy * sp * sr - sy * cr; tl[2] = cy * sp * cr + sy * sr;
        tl[3] = sy * cp; tl[4] = sy * sp * sr + cy * cr; tl[5] = sy * sp * cr - cy * sr;
        tl[6] = -sp;     tl[7] = cp * sr;                tl[8] = cp * cr;
        tl[9] = pos[idx * 3 + 0]; tl[10] = pos[idx * 3 + 1]; tl[11] = pos[idx * 3 + 2];
    }

    // ---------------- stage q into shared (coalesced) ----------------
    if (nel == THREADS) {
        const float4* gq = (const float4*)(q + (long long)b0 * 24);
        #pragma unroll
        for (int i4 = tid; i4 < THREADS * 24 / 4; i4 += THREADS) {
            float4 v = gq[i4];
            int i = i4 * 4;
            int e = i / 24, r = i - e * 24;
            float* d = s_q + e * QSTRIDE + r;
            d[0] = v.x; d[1] = v.y; d[2] = v.z; d[3] = v.w;
        }
    } else {
        for (int i = tid; i < nel * 24; i += THREADS) {
            int e = i / 24, r = i - e * 24;
            s_q[e * QSTRIDE + r] = q[(long long)b0 * 24 + i];
        }
    }
    __syncthreads();

    const long long b = (long long)b0 + tid;
    const bool active = (b < B);
    const float* sqBase = s_q + tid * QSTRIDE;
    float* srevBase = s_rev + tid * CSTRIDE;
    float* spriBase = s_pri + tid * CSTRIDE;
    float* revg = out + (long long)B * 48 + (long long)b0 * 72;
    float* prig = out + (long long)B * 120 + (long long)b0 * 72;

    // persistent transform state
    float R00 = 1.f, R01 = 0.f, R02 = 0.f;
    float R10 = 0.f, R11 = 1.f, R12 = 0.f;
    float R20 = 0.f, R21 = 0.f, R22 = 1.f;
    float px = 0.f, py = 0.f, pz = 0.f;

    #pragma unroll
    for (int jc = 0; jc < 3; jc++) {     // 4 joints per chunk
        if (active) {
            #pragma unroll
            for (int jj = 0; jj < 4; jj++) {
                int j = jc * 4 + jj;
                #pragma unroll
                for (int half = 0; half < 2; half++) {
                    const float* t = s_tw + (2 * j + half) * 24;
                    float wx = t[0], wy = t[1], wz = t[2];
                    float vx = t[3], vy = t[4], vz = t[5];

                    // adj_inv(T) applied to xi
                    float wpx = R00 * wx + R10 * wy + R20 * wz;
                    float wpy = R01 * wx + R11 * wy + R21 * wz;
                    float wpz = R02 * wx + R12 * wy + R22 * wz;
                    float ux = vx - (py * wz - pz * wy);
                    float uy = vy - (pz * wx - px * wz);
                    float uz = vz - (px * wy - py * wx);
                    float vpx = R00 * ux + R10 * uy + R20 * uz;
                    float vpy = R01 * ux + R11 * uy + R21 * uz;
                    float vpz = R02 * ux + R12 * uy + R22 * uz;
                    float* sdst = (half ? spriBase : srevBase) + jj * 6;
                    sdst[0] = wpx; sdst[1] = wpy; sdst[2] = wpz;
                    sdst[3] = vpx; sdst[4] = vpy; sdst[5] = vpz;

                    // E = exp(xi * th)
                    float th = sqBase[2 * j + half];
                    float ang = t[6] * th;
                    float s, c;
                    __sincosf(ang, &s, &c);
                    float k1 = s * t[19];
                    float k2 = (1.0f - c) * t[20];
                    float k3 = (ang - s) * t[21];
                    float E00 = 1.f + k2 * t[7];
                    float E01 = -k1 * wz + k2 * t[8];
                    float E02 =  k1 * wy + k2 * t[9];
                    float E10 =  k1 * wz + k2 * t[8];
                    float E11 = 1.f + k2 * t[10];
                    float E12 = -k1 * wx + k2 * t[11];
                    float E20 = -k1 * wy + k2 * t[9];
                    float E21 =  k1 * wx + k2 * t[11];
                    float E22 = 1.f + k2 * t[12];
                    float ex = th * vx + k2 * t[13] + k3 * t[16];
                    float ey = th * vy + k2 * t[14] + k3 * t[17];
                    float ez = th * vz + k2 * t[15] + k3 * t[18];

                    // T = T * E
                    float npx = px + R00 * ex + R01 * ey + R02 * ez;
                    float npy = py + R10 * ex + R11 * ey + R12 * ez;
                    float npz = pz + R20 * ex + R21 * ey + R22 * ez;
                    float n00 = R00 * E00 + R01 * E10 + R02 * E20;
                    float n01 = R00 * E01 + R01 * E11 + R02 * E21;
                    float n02 = R00 * E02 + R01 * E12 + R02 * E22;
                    float n10 = R10 * E00 + R11 * E10 + R12 * E20;
                    float n11 = R10 * E01 + R11 * E11 + R12 * E21;
                    float n12 = R10 * E02 + R11 * E12 + R12 * E22;
                    float n20 = R20 * E00 + R21 * E10 + R22 * E20;
                    float n21 = R20 * E01 + R21 * E11 + R22 * E21;
                    float n22 = R20 * E02 + R21 * E12 + R22 * E22;
                    R00 = n00; R01 = n01; R02 = n02;
                    R10 = n10; R11 = n11; R12 = n12;
                    R20 = n20; R21 = n21; R22 = n22;
                    px = npx; py = npy; pz = npz;

                    // branch outputs at j = 3, 7, 11
                    if (half == 1 && (j & 3) == 3) {
                        int k = j >> 2;
                        const float* tl = s_tool + k * 12;
                        float O00 = R00 * tl[0] + R01 * tl[3] + R02 * tl[6];
                        float O01 = R00 * tl[1] + R01 * tl[4] + R02 * tl[7];
                        float O02 = R00 * tl[2] + R01 * tl[5] + R02 * tl[8];
                        float O10 = R10 * tl[0] + R11 * tl[3] + R12 * tl[6];
                        float O11 = R10 * tl[1] + R11 * tl[4] + R12 * tl[7];
                        float O12 = R10 * tl[2] + R11 * tl[5] + R12 * tl[8];
                        float O20 = R20 * tl[0] + R21 * tl[3] + R22 * tl[6];
                        float O21 = R20 * tl[1] + R21 * tl[4] + R22 * tl[7];
                        float O22 = R20 * tl[2] + R21 * tl[5] + R22 * tl[8];
                        float pox = R00 * tl[9] + R01 * tl[10] + R02 * tl[11] + px;
                        float poy = R10 * tl[9] + R11 * tl[10] + R12 * tl[11] + py;
                        float poz = R20 * tl[9] + R21 * tl[10] + R22 * tl[11] + pz;
                        float4* dst = (float4*)(out + b * 48 + k * 16);
                        dst[0] = make_float4(O00, O01, O02, pox);
                        dst[1] = make_float4(O10, O11, O12, poy);
                        dst[2] = make_float4(O20, O21, O22, poz);
                        dst[3] = make_float4(0.f, 0.f, 0.f, 1.f);
                    }
                }
            }
        }
        __syncthreads();

        // ---- flush this 4-joint chunk (coalesced float4 global stores) ----
        if (nel == THREADS) {
            float4* r4 = (float4*)revg;
            float4* p4 = (float4*)prig;
            #pragma unroll
            for (int i4 = tid; i4 < THREADS * 6; i4 += THREADS) {
                int e = i4 / 6, r = i4 - e * 6;       // 6 float4 = 24 floats per element
                int gidx = e * 18 + jc * 6 + r;       // element block = 18 float4
                const float* sa = s_rev + e * CSTRIDE + r * 4;
                r4[gidx] = make_float4(sa[0], sa[1], sa[2], sa[3]);
                const float* sb = s_pri + e * CSTRIDE + r * 4;
                p4[gidx] = make_float4(sb[0], sb[1], sb[2], sb[3]);
            }
        } else {
            for (int i = tid; i < nel * 24; i += THREADS) {
                int e = i / 24, r = i - e * 24;
                revg[e * 72 + jc * 24 + r] = s_rev[e * CSTRIDE + r];
                prig[e * 72 + jc * 24 + r] = s_pri[e * CSTRIDE + r];
            }
        }
        if (jc < 2) __syncthreads();   // staging buffers reused by next chunk
    }
}

extern "C" void kernel_launch(void* const* d_in, const int* in_sizes, int n_in,
                              void* d_out, int out_size)
{
    const float* q   = (const float*)d_in[0];
    const float* rev = (const float*)d_in[1];
    const float* pri = (const float*)d_in[2];
    const float* pos = (const float*)d_in[3];
    const float* ori = (const float*)d_in[4];
    float* out = (float*)d_out;
    int B = in_sizes[0] / 24;
    int grid = (B + THREADS - 1) / THREADS;
    poe_kernel<<<grid, THREADS>>>(q, rev, pri, pos, ori, out, B);
}

// round 9
// speedup vs baseline: 4.4146x; 1.0332x over previous
#include <cuda_runtime.h>
#include <math.h>

#define THREADS 64
#define QSTRIDE 25   // 24 q values + 1 pad (conflict-free, odd)
#define CSTRIDE 25   // 4 joints * 6 floats + 1 pad (conflict-free, odd)
#define OSTRIDE 17   // 16 outs floats + 1 pad (conflict-free, odd)

// Output layout (flattened tuple, float32):
//   outs : [B][3][4][4]  at offset 0            (B*48)
//   revls: [B][12][6]    at offset B*48         (B*72)
//   prils: [B][12][6]    at offset B*120        (B*72)

__global__ __launch_bounds__(THREADS, 8) void poe_kernel(
    const float* __restrict__ q,
    const float* __restrict__ rev,
    const float* __restrict__ pri,
    const float* __restrict__ pos,
    const float* __restrict__ ori,
    float* __restrict__ out, int B)
{
    __shared__ float s_tw[24 * 24];            // 6 float4 per twist
    __shared__ float s_tool[3 * 12];
    __shared__ float s_q[THREADS * QSTRIDE];
    __shared__ float s_rev[THREADS * CSTRIDE];
    __shared__ float s_pri[THREADS * CSTRIDE];
    __shared__ float s_out[THREADS * OSTRIDE];

    const int tid = threadIdx.x;
    const int b0 = blockIdx.x * THREADS;
    const int nel = min(B - b0, THREADS);

    // ---------------- setup: twist constants ----------------
    if (tid < 24) {
        int j = tid >> 1;
        const float* xi = (tid & 1) ? (pri + j * 6) : (rev + j * 6);
        float wx = xi[0], wy = xi[1], wz = xi[2];
        float vx = xi[3], vy = xi[4], vz = xi[5];
        float ww = wx * wx + wy * wy + wz * wz;
        float a2 = ww + 1e-12f;
        float a = sqrtf(a2);
        float inva = 1.0f / a;
        float inva2 = 1.0f / a2;
        float* t = s_tw + tid * 24;
        // packed for float4 reads:
        // t4[0] = {wx, wy, wz, a}
        // t4[1] = {vx, vy, vz, inva}
        // t4[2] = {W2xx, W2xy, W2xz, inva2}
        // t4[3] = {W2yy, W2yz, W2zz, inva3}
        // t4[4] = {wxv_x, wxv_y, wxv_z, 0}
        // t4[5] = {W2v_x, W2v_y, W2v_z, 0}
        float W2xx = wx * wx - ww, W2xy = wx * wy, W2xz = wx * wz;
        float W2yy = wy * wy - ww, W2yz = wy * wz, W2zz = wz * wz - ww;
        t[0] = wx;  t[1] = wy;  t[2] = wz;  t[3] = a;
        t[4] = vx;  t[5] = vy;  t[6] = vz;  t[7] = inva;
        t[8] = W2xx; t[9] = W2xy; t[10] = W2xz; t[11] = inva2;
        t[12] = W2yy; t[13] = W2yz; t[14] = W2zz; t[15] = inva * inva2;
        t[16] = wy * vz - wz * vy;
        t[17] = wz * vx - wx * vz;
        t[18] = wx * vy - wy * vx;
        t[19] = 0.f;
        t[20] = W2xx * vx + W2xy * vy + W2xz * vz;
        t[21] = W2xy * vx + W2yy * vy + W2yz * vz;
        t[22] = W2xz * vx + W2yz * vy + W2zz * vz;
        t[23] = 0.f;
    } else if (tid < 27) {
        int k = tid - 24;
        int idx = 4 * k + 3;
        float rr = ori[idx * 3 + 0], pp = ori[idx * 3 + 1], yy = ori[idx * 3 + 2];
        float cr, sr, cp, sp, cy, sy;
        sincosf(rr, &sr, &cr);
        sincosf(pp, &sp, &cp);
        sincosf(yy, &sy, &cy);
        float* tl = s_tool + k * 12;
        tl[0] = cy * cp; tl[1] = cy * sp * sr - sy * cr; tl[2] = cy * sp * cr + sy * sr;
        tl[3] = sy * cp; tl[4] = sy * sp * sr + cy * cr; tl[5] = sy * sp * cr - cy * sr;
        tl[6] = -sp;     tl[7] = cp * sr;                tl[8] = cp * cr;
        tl[9] = pos[idx * 3 + 0]; tl[10] = pos[idx * 3 + 1]; tl[11] = pos[idx * 3 + 2];
    }

    // ---------------- stage q into shared (coalesced) ----------------
    if (nel == THREADS) {
        const float4* gq = (const float4*)(q + (long long)b0 * 24);
        #pragma unroll
        for (int i4 = tid; i4 < THREADS * 24 / 4; i4 += THREADS) {
            float4 v = gq[i4];
            int i = i4 * 4;
            int e = i / 24, r = i - e * 24;
            float* d = s_q + e * QSTRIDE + r;
            d[0] = v.x; d[1] = v.y; d[2] = v.z; d[3] = v.w;
        }
    } else {
        for (int i = tid; i < nel * 24; i += THREADS) {
            int e = i / 24, r = i - e * 24;
            s_q[e * QSTRIDE + r] = q[(long long)b0 * 24 + i];
        }
    }
    __syncthreads();

    const long long b = (long long)b0 + tid;
    const bool active = (b < B);
    const float* sqBase = s_q + tid * QSTRIDE;
    float* srevBase = s_rev + tid * CSTRIDE;
    float* spriBase = s_pri + tid * CSTRIDE;
    float* soutBase = s_out + tid * OSTRIDE;
    float* revg = out + (long long)B * 48 + (long long)b0 * 72;
    float* prig = out + (long long)B * 120 + (long long)b0 * 72;

    // persistent transform state
    float R00 = 1.f, R01 = 0.f, R02 = 0.f;
    float R10 = 0.f, R11 = 1.f, R12 = 0.f;
    float R20 = 0.f, R21 = 0.f, R22 = 1.f;
    float px = 0.f, py = 0.f, pz = 0.f;

    #pragma unroll
    for (int jc = 0; jc < 3; jc++) {     // 4 joints per chunk; branch at chunk end
        if (active) {
            #pragma unroll
            for (int jj = 0; jj < 4; jj++) {
                int j = jc * 4 + jj;
                #pragma unroll
                for (int half = 0; half < 2; half++) {
                    const float4* t4 = (const float4*)(s_tw + (2 * j + half) * 24);
                    float4 tA = t4[0];   // wx wy wz a
                    float4 tB = t4[1];   // vx vy vz 1/a
                    float wx = tA.x, wy = tA.y, wz = tA.z;
                    float vx = tB.x, vy = tB.y, vz = tB.z;

                    // adj_inv(T) applied to xi
                    float wpx = R00 * wx + R10 * wy + R20 * wz;
                    float wpy = R01 * wx + R11 * wy + R21 * wz;
                    float wpz = R02 * wx + R12 * wy + R22 * wz;
                    float ux = vx - (py * wz - pz * wy);
                    float uy = vy - (pz * wx - px * wz);
                    float uz = vz - (px * wy - py * wx);
                    float vpx = R00 * ux + R10 * uy + R20 * uz;
                    float vpy = R01 * ux + R11 * uy + R21 * uz;
                    float vpz = R02 * ux + R12 * uy + R22 * uz;
                    float* sdst = (half ? spriBase : srevBase) + jj * 6;
                    sdst[0] = wpx; sdst[1] = wpy; sdst[2] = wpz;
                    sdst[3] = vpx; sdst[4] = vpy; sdst[5] = vpz;

                    // E = exp(xi * th)
                    float4 tC = t4[2];   // W2xx W2xy W2xz 1/a^2
                    float4 tD = t4[3];   // W2yy W2yz W2zz 1/a^3
                    float4 tE = t4[4];   // w x v
                    float4 tF = t4[5];   // W2 @ v
                    float th = sqBase[2 * j + half];
                    float ang = tA.w * th;
                    float s, c;
                    __sincosf(ang, &s, &c);
                    float k1 = s * tB.w;
                    float k2 = (1.0f - c) * tC.w;
                    float k3 = (ang - s) * tD.w;
                    float E00 = 1.f + k2 * tC.x;
                    float E01 = -k1 * wz + k2 * tC.y;
                    float E02 =  k1 * wy + k2 * tC.z;
                    float E10 =  k1 * wz + k2 * tC.y;
                    float E11 = 1.f + k2 * tD.x;
                    float E12 = -k1 * wx + k2 * tD.y;
                    float E20 = -k1 * wy + k2 * tC.z;
                    float E21 =  k1 * wx + k2 * tD.y;
                    float E22 = 1.f + k2 * tD.z;
                    float ex = th * vx + k2 * tE.x + k3 * tF.x;
                    float ey = th * vy + k2 * tE.y + k3 * tF.y;
                    float ez = th * vz + k2 * tE.z + k3 * tF.z;

                    // T = T * E
                    float npx = px + R00 * ex + R01 * ey + R02 * ez;
                    float npy = py + R10 * ex + R11 * ey + R12 * ez;
                    float npz = pz + R20 * ex + R21 * ey + R22 * ez;
                    float n00 = R00 * E00 + R01 * E10 + R02 * E20;
                    float n01 = R00 * E01 + R01 * E11 + R02 * E21;
                    float n02 = R00 * E02 + R01 * E12 + R02 * E22;
                    float n10 = R10 * E00 + R11 * E10 + R12 * E20;
                    float n11 = R10 * E01 + R11 * E11 + R12 * E21;
                    float n12 = R10 * E02 + R11 * E12 + R12 * E22;
                    float n20 = R20 * E00 + R21 * E10 + R22 * E20;
                    float n21 = R20 * E01 + R21 * E11 + R22 * E21;
                    float n22 = R20 * E02 + R21 * E12 + R22 * E22;
                    R00 = n00; R01 = n01; R02 = n02;
                    R10 = n10; R11 = n11; R12 = n12;
                    R20 = n20; R21 = n21; R22 = n22;
                    px = npx; py = npy; pz = npz;
                }
            }

            // branch output (j = 4jc+3) -> staged to smem
            {
                int k = jc;
                const float* tl = s_tool + k * 12;
                float O00 = R00 * tl[0] + R01 * tl[3] + R02 * tl[6];
                float O01 = R00 * tl[1] + R01 * tl[4] + R02 * tl[7];
                float O02 = R00 * tl[2] + R01 * tl[5] + R02 * tl[8];
                float O10 = R10 * tl[0] + R11 * tl[3] + R12 * tl[6];
                float O11 = R10 * tl[1] + R11 * tl[4] + R12 * tl[7];
                float O12 = R10 * tl[2] + R11 * tl[5] + R12 * tl[8];
                float O20 = R20 * tl[0] + R21 * tl[3] + R22 * tl[6];
                float O21 = R20 * tl[1] + R21 * tl[4] + R22 * tl[7];
                float O22 = R20 * tl[2] + R21 * tl[5] + R22 * tl[8];
                float pox = R00 * tl[9] + R01 * tl[10] + R02 * tl[11] + px;
                float poy = R10 * tl[9] + R11 * tl[10] + R12 * tl[11] + py;
                float poz = R20 * tl[9] + R21 * tl[10] + R22 * tl[11] + pz;
                soutBase[0]  = O00; soutBase[1]  = O01; soutBase[2]  = O02; soutBase[3]  = pox;
                soutBase[4]  = O10; soutBase[5]  = O11; soutBase[6]  = O12; soutBase[7]  = poy;
                soutBase[8]  = O20; soutBase[9]  = O21; soutBase[10] = O22; soutBase[11] = poz;
                soutBase[12] = 0.f; soutBase[13] = 0.f; soutBase[14] = 0.f; soutBase[15] = 1.f;
            }
        }
        __syncthreads();

        // ---- flush this chunk: rev/pri (24 floats/el) + outs (16 floats/el) ----
        if (nel == THREADS) {
            float4* r4 = (float4*)revg;
            float4* p4 = (float4*)prig;
            #pragma unroll
            for (int i4 = tid; i4 < THREADS * 6; i4 += THREADS) {
                int e = i4 / 6, r = i4 - e * 6;
                int gidx = e * 18 + jc * 6 + r;
                const float* sa = s_rev + e * CSTRIDE + r * 4;
                r4[gidx] = make_float4(sa[0], sa[1], sa[2], sa[3]);
                const float* sb = s_pri + e * CSTRIDE + r * 4;
                p4[gidx] = make_float4(sb[0], sb[1], sb[2], sb[3]);
            }
            float4* o4 = (float4*)(out + (long long)b0 * 48);
            #pragma unroll
            for (int i4 = tid; i4 < THREADS * 4; i4 += THREADS) {
                int e = i4 >> 2, r = i4 & 3;
                const float* sc = s_out + e * OSTRIDE + r * 4;
                o4[e * 12 + jc * 4 + r] = make_float4(sc[0], sc[1], sc[2], sc[3]);
            }
        } else {
            for (int i = tid; i < nel * 24; i += THREADS) {
                int e = i / 24, r = i - e * 24;
                revg[e * 72 + jc * 24 + r] = s_rev[e * CSTRIDE + r];
                prig[e * 72 + jc * 24 + r] = s_pri[e * CSTRIDE + r];
            }
            for (int i = tid; i < nel * 16; i += THREADS) {
                int e = i / 16, r = i - e * 16;
                out[(long long)(b0 + e) * 48 + jc * 16 + r] = s_out[e * OSTRIDE + r];
            }
        }
        if (jc < 2) __syncthreads();   // staging buffers reused by next chunk
    }
}

extern "C" void kernel_launch(void* const* d_in, const int* in_sizes, int n_in,
                              void* d_out, int out_size)
{
    const float* q   = (const float*)d_in[0];
    const float* rev = (const float*)d_in[1];
    const float* pri = (const float*)d_in[2];
    const float* pos = (const float*)d_in[3];
    const float* ori = (const float*)d_in[4];
    float* out = (float*)d_out;
    int B = in_sizes[0] / 24;
    int grid = (B + THREADS - 1) / THREADS;
    poe_kernel<<<grid, THREADS>>>(q, rev, pri, pos, ori, out, B);
}